// round 2
// baseline (speedup 1.0000x reference)
#include <cuda_runtime.h>
#include <cuda_bf16.h>
#include <math.h>

#define Bq   8
#define Tq   2048
#define Dq   1024
#define HSq  128
#define BT   (Bq * Tq)        // 16384 rows

// Scratch for projected q, k, v (fp32). __device__ globals per harness rules.
__device__ float g_q[BT * HSq];
__device__ float g_k[BT * HSq];
__device__ float g_v[BT * HSq];

// ---------------------------------------------------------------------------
// Kernel 1: fused QKV projection.
// GEMM: [16384 x 1024] @ [1024 x 384] -> g_q | g_k | g_v
// Grid: (BT/64, 6). Block 256 threads. BM=64, BN=64, BK=32.
// Thread micro-tile: 4 rows (ty*4+i) x 4 cols (tx + 16*j, strided -> conflict-free LDS)
// ---------------------------------------------------------------------------
__global__ __launch_bounds__(256) void proj_kernel(
    const float* __restrict__ x,
    const float* __restrict__ Wq,
    const float* __restrict__ Wk,
    const float* __restrict__ Wv)
{
    __shared__ float Xs[64][33];
    __shared__ float Ws[32][65];

    const int m0 = blockIdx.x * 64;
    const int nt = blockIdx.y;                    // 0..5 -> which 64-col slab of [q|k|v]
    const float* W = (nt < 2) ? Wq : (nt < 4) ? Wk : Wv;
    float* outp    = (nt < 2) ? g_q : (nt < 4) ? g_k : g_v;
    const int ncol0 = (nt & 1) * 64;              // col offset within HS=128

    const int tid = threadIdx.x;
    const int tx = tid & 15;
    const int ty = tid >> 4;

    float acc[4][4] = {};

    for (int kt = 0; kt < Dq; kt += 32) {
        // Load Xs: 64x32 floats = 512 float4, 2 per thread
        #pragma unroll
        for (int it = 0; it < 2; it++) {
            int idx = tid + it * 256;
            int r  = idx >> 3;         // 8 float4 per row
            int c4 = (idx & 7) * 4;
            float4 v = *(const float4*)&x[(size_t)(m0 + r) * Dq + kt + c4];
            Xs[r][c4 + 0] = v.x; Xs[r][c4 + 1] = v.y;
            Xs[r][c4 + 2] = v.z; Xs[r][c4 + 3] = v.w;
        }
        // Load Ws: 32x64 floats = 512 float4, 2 per thread
        #pragma unroll
        for (int it = 0; it < 2; it++) {
            int idx = tid + it * 256;
            int r  = idx >> 4;         // 16 float4 per row
            int c4 = (idx & 15) * 4;
            float4 v = *(const float4*)&W[(size_t)(kt + r) * HSq + ncol0 + c4];
            Ws[r][c4 + 0] = v.x; Ws[r][c4 + 1] = v.y;
            Ws[r][c4 + 2] = v.z; Ws[r][c4 + 3] = v.w;
        }
        __syncthreads();

        #pragma unroll 8
        for (int kk = 0; kk < 32; kk++) {
            float a[4], b[4];
            #pragma unroll
            for (int i = 0; i < 4; i++) a[i] = Xs[ty * 4 + i][kk];
            #pragma unroll
            for (int j = 0; j < 4; j++) b[j] = Ws[kk][tx + 16 * j];
            #pragma unroll
            for (int i = 0; i < 4; i++)
                #pragma unroll
                for (int j = 0; j < 4; j++)
                    acc[i][j] = fmaf(a[i], b[j], acc[i][j]);
        }
        __syncthreads();
    }

    #pragma unroll
    for (int i = 0; i < 4; i++)
        #pragma unroll
        for (int j = 0; j < 4; j++)
            outp[(size_t)(m0 + ty * 4 + i) * HSq + ncol0 + tx + 16 * j] = acc[i][j];
}

// ---------------------------------------------------------------------------
// Kernel 2: causal flash attention, fp32.
// Grid: (16 pairs, 8 batches). Block 256 threads.
// Each block processes q-tiles pair (p) and (31-p): constant 33 KV iterations
// per block -> balanced single wave.
// smem: Qs/Ks/Vs 64x128 padded to stride 129. P aliases Ks.
// ---------------------------------------------------------------------------
#define SM_STRIDE 129
#define ATTN_SMEM (3 * 64 * SM_STRIDE * sizeof(float))

__global__ __launch_bounds__(256) void attn_kernel(float* __restrict__ out)
{
    extern __shared__ float sm[];
    float (*Qs)[SM_STRIDE] = (float (*)[SM_STRIDE])(sm);
    float (*Ks)[SM_STRIDE] = (float (*)[SM_STRIDE])(sm + 64 * SM_STRIDE);
    float (*Vs)[SM_STRIDE] = (float (*)[SM_STRIDE])(sm + 2 * 64 * SM_STRIDE);
    float (*Ps)[SM_STRIDE] = Ks;   // P overwrites K after S-gemm

    const int b    = blockIdx.y;
    const int pair = blockIdx.x;          // 0..15
    const int tid  = threadIdx.x;
    const int tx   = tid & 15;
    const int ty   = tid >> 4;

    const float* qg = g_q + (size_t)b * Tq * HSq;
    const float* kg = g_k + (size_t)b * Tq * HSq;
    const float* vg = g_v + (size_t)b * Tq * HSq;

    const float scale = 0.08838834764831845f;   // 128^-0.5
    const float NEG_INF = -__int_as_float(0x7f800000);

    for (int half = 0; half < 2; half++) {
        const int qt = (half == 0) ? pair : (31 - pair);
        const int q0 = qt * 64;

        __syncthreads();  // previous half's smem reads are done
        // Load Q tile (fold softmax scale into Q)
        #pragma unroll
        for (int it = 0; it < 8; it++) {
            int idx = tid + it * 256;
            int r  = idx >> 5;           // 32 float4 per row
            int c4 = (idx & 31) * 4;
            float4 v = *(const float4*)&qg[(size_t)(q0 + r) * HSq + c4];
            Qs[r][c4 + 0] = v.x * scale; Qs[r][c4 + 1] = v.y * scale;
            Qs[r][c4 + 2] = v.z * scale; Qs[r][c4 + 3] = v.w * scale;
        }

        float acc_o[4][8] = {};
        float m_i[4], l_i[4];
        #pragma unroll
        for (int i = 0; i < 4; i++) { m_i[i] = NEG_INF; l_i[i] = 0.f; }

        const int ktiles = qt + 1;
        for (int kt = 0; kt < ktiles; kt++) {
            const int k0 = kt * 64;

            __syncthreads();  // prior PV reads of Ps(=Ks)/Vs done; Q load done
            // Load K and V tiles
            #pragma unroll
            for (int it = 0; it < 8; it++) {
                int idx = tid + it * 256;
                int r  = idx >> 5;
                int c4 = (idx & 31) * 4;
                float4 kv = *(const float4*)&kg[(size_t)(k0 + r) * HSq + c4];
                Ks[r][c4 + 0] = kv.x; Ks[r][c4 + 1] = kv.y;
                Ks[r][c4 + 2] = kv.z; Ks[r][c4 + 3] = kv.w;
                float4 vv = *(const float4*)&vg[(size_t)(k0 + r) * HSq + c4];
                Vs[r][c4 + 0] = vv.x; Vs[r][c4 + 1] = vv.y;
                Vs[r][c4 + 2] = vv.z; Vs[r][c4 + 3] = vv.w;
            }
            __syncthreads();

            // S = Q K^T  (64x64, per-thread 4x4; n mapping tx+16j)
            float s[4][4] = {};
            #pragma unroll 8
            for (int kk = 0; kk < HSq; kk++) {
                float a[4], bb[4];
                #pragma unroll
                for (int i = 0; i < 4; i++) a[i] = Qs[ty * 4 + i][kk];
                #pragma unroll
                for (int j = 0; j < 4; j++) bb[j] = Ks[tx + 16 * j][kk];
                #pragma unroll
                for (int i = 0; i < 4; i++)
                    #pragma unroll
                    for (int j = 0; j < 4; j++)
                        s[i][j] = fmaf(a[i], bb[j], s[i][j]);
            }

            // Causal mask only on the diagonal tile
            if (kt == qt) {
                #pragma unroll
                for (int i = 0; i < 4; i++)
                    #pragma unroll
                    for (int j = 0; j < 4; j++)
                        if ((tx + 16 * j) > (ty * 4 + i)) s[i][j] = NEG_INF;
            }

            // Online softmax (per row i; 16-lane shfl reductions)
            #pragma unroll
            for (int i = 0; i < 4; i++) {
                float mx = s[i][0];
                mx = fmaxf(mx, s[i][1]); mx = fmaxf(mx, s[i][2]); mx = fmaxf(mx, s[i][3]);
                #pragma unroll
                for (int off = 8; off >= 1; off >>= 1)
                    mx = fmaxf(mx, __shfl_xor_sync(0xffffffffu, mx, off));
                float m_new = fmaxf(m_i[i], mx);
                float alpha = __expf(m_i[i] - m_new);
                float rs = 0.f;
                #pragma unroll
                for (int j = 0; j < 4; j++) {
                    float p = __expf(s[i][j] - m_new);
                    s[i][j] = p;
                    rs += p;
                }
                #pragma unroll
                for (int off = 8; off >= 1; off >>= 1)
                    rs += __shfl_xor_sync(0xffffffffu, rs, off);
                l_i[i] = l_i[i] * alpha + rs;
                m_i[i] = m_new;
                #pragma unroll
                for (int jj = 0; jj < 8; jj++) acc_o[i][jj] *= alpha;
            }

            __syncthreads();  // all S-gemm reads of Ks done before overwriting with P
            #pragma unroll
            for (int i = 0; i < 4; i++)
                #pragma unroll
                for (int j = 0; j < 4; j++)
                    Ps[ty * 4 + i][tx + 16 * j] = s[i][j];
            __syncthreads();

            // O += P @ V   (64x128, per-thread 4 rows x 8 cols [tx+16jj])
            #pragma unroll 4
            for (int n = 0; n < 64; n++) {
                float pr[4], vv[8];
                #pragma unroll
                for (int i = 0; i < 4; i++) pr[i] = Ps[ty * 4 + i][n];
                #pragma unroll
                for (int jj = 0; jj < 8; jj++) vv[jj] = Vs[n][tx + 16 * jj];
                #pragma unroll
                for (int i = 0; i < 4; i++)
                    #pragma unroll
                    for (int jj = 0; jj < 8; jj++)
                        acc_o[i][jj] = fmaf(pr[i], vv[jj], acc_o[i][jj]);
            }
        }

        // Epilogue: normalize and store
        #pragma unroll
        for (int i = 0; i < 4; i++) {
            float inv = __frcp_rn(l_i[i]);
            int row = q0 + ty * 4 + i;
            #pragma unroll
            for (int jj = 0; jj < 8; jj++)
                out[((size_t)b * Tq + row) * HSq + tx + 16 * jj] = acc_o[i][jj] * inv;
        }
    }
}

// ---------------------------------------------------------------------------
extern "C" void kernel_launch(void* const* d_in, const int* in_sizes, int n_in,
                              void* d_out, int out_size)
{
    const float* x  = (const float*)d_in[0];
    const float* Wq = (const float*)d_in[1];
    const float* Wk = (const float*)d_in[2];
    const float* Wv = (const float*)d_in[3];
    float* out = (float*)d_out;

    cudaFuncSetAttribute(attn_kernel, cudaFuncAttributeMaxDynamicSharedMemorySize,
                         (int)ATTN_SMEM);

    dim3 pgrid(BT / 64, 6);
    proj_kernel<<<pgrid, 256>>>(x, Wq, Wk, Wv);

    dim3 agrid(16, Bq);
    attn_kernel<<<agrid, 256, ATTN_SMEM>>>(out);
}